// round 1
// baseline (speedup 1.0000x reference)
#include <cuda_runtime.h>

#define NQ 16384
#define NF 8192
#define DD 64
#define KNN 5
#define NC 32

#define INFF __int_as_float(0x7f800000)

// ---------------- device scratch (static, no allocation) ----------------
__device__ unsigned long long g_qmask[NQ];   // bit c = 1 if X[q,c] observed
__device__ unsigned long long g_dmask[NF];   // bit c = 1 if fit[j,c] observed
__device__ float g_colmean[DD];
__device__ float g_ckey[NQ * NC];
__device__ int   g_cidx[NQ * NC];

__device__ __forceinline__ bool obs_f(float v) {
    // !isnan, robust to fast-math: NaN iff (bits & 0x7fffffff) > 0x7f800000
    return (__float_as_uint(v) & 0x7fffffffu) <= 0x7f800000u;
}

// ---------------- kernel 0: observation bitmasks -------------------------
__global__ void masks_kernel(const float* __restrict__ X, const float* __restrict__ F) {
    int row  = blockIdx.x * 8 + (threadIdx.x >> 5);
    int lane = threadIdx.x & 31;
    const float* p;
    unsigned long long* o;
    int r;
    if (row < NQ)            { p = X; o = g_qmask; r = row; }
    else if (row < NQ + NF)  { p = F; o = g_dmask; r = row - NQ; }
    else return;
    float v0 = p[r * 64 + lane];
    float v1 = p[r * 64 + 32 + lane];
    unsigned lo = __ballot_sync(0xffffffffu, obs_f(v0));
    unsigned hi = __ballot_sync(0xffffffffu, obs_f(v1));
    if (lane == 0) o[r] = (unsigned long long)lo | ((unsigned long long)hi << 32);
}

// ---------------- kernel 1: per-column means of fit (fallback path) ------
__global__ void colmean_kernel(const float* __restrict__ F) {
    int c = blockIdx.x;
    float s = 0.f, n = 0.f;
    for (int r = threadIdx.x; r < NF; r += blockDim.x) {
        float v = F[r * 64 + c];
        if (obs_f(v)) { s += v; n += 1.f; }
    }
    __shared__ float ss[256], sn[256];
    ss[threadIdx.x] = s; sn[threadIdx.x] = n;
    __syncthreads();
    for (int st = 128; st > 0; st >>= 1) {
        if (threadIdx.x < st) {
            ss[threadIdx.x] += ss[threadIdx.x + st];
            sn[threadIdx.x] += sn[threadIdx.x + st];
        }
        __syncthreads();
    }
    if (threadIdx.x == 0) g_colmean[c] = ss[0] / fmaxf(sn[0], 1.f);
}

// ---------------- kernel 2: fused masked distances + global top-32 -------
// CTA: 128 queries x all 8192 donors (64 tiles of 128). 256 threads,
// each computes an 8x8 distance sub-tile. FMA-pipe bound by design.
__global__ __launch_bounds__(256) void dist_topk_kernel(const float* __restrict__ X,
                                                        const float* __restrict__ F) {
    extern __shared__ float sm[];
    float* sA    = sm;              // [64][128] cleaned query values
    float* sMa   = sm + 8192;       // [64][128] query observed mask (0/1)
    float* sB    = sm + 16384;      // [64][128] cleaned donor values
    float* sMb   = sm + 24576;      // [64][128] donor mask
    float* sDist = sm + 16384;      // [128][128] keys (aliases sB/sMb after sync)
    float* sKey  = sm + 32768;      // [128][32] running top-32 keys
    int*   sIdx  = (int*)(sm + 36864); // [128][32] donor indices

    const int tid = threadIdx.x;
    const int ty = tid >> 4, tx = tid & 15;
    const int q0 = blockIdx.x * 128;

    // load query tile (clean + mask), transposed [d][q]
    for (int i = tid; i < 8192; i += 256) {
        int ql = i >> 6, d = i & 63;
        float v = X[(q0 + ql) * 64 + d];
        bool ob = obs_f(v);
        sA [d * 128 + ql] = ob ? v : 0.f;
        sMa[d * 128 + ql] = ob ? 1.f : 0.f;
    }
    if (tid < 128) {
        #pragma unroll
        for (int k = 0; k < NC; ++k) {
            sKey[tid * NC + k] = INFF;
            sIdx[tid * NC + k] = 0x7fffffff;
        }
    }
    unsigned long long qm[8];
    #pragma unroll
    for (int i = 0; i < 8; ++i) {
        int qi = ((i & 3) + ty * 4) + ((i >> 2) << 6);
        qm[i] = g_qmask[q0 + qi];
    }
    float curMax = INFF; int curPos = 0;
    __syncthreads();

    for (int t = 0; t < 64; ++t) {
        const int jb = t * 128;
        // load donor tile
        for (int i = tid; i < 8192; i += 256) {
            int jl = i >> 6, d = i & 63;
            float v = F[(jb + jl) * 64 + d];
            bool ob = obs_f(v);
            sB [d * 128 + jl] = ob ? v : 0.f;
            sMb[d * 128 + jl] = ob ? 1.f : 0.f;
        }
        unsigned long long dmsk[8];
        #pragma unroll
        for (int j = 0; j < 8; ++j) {
            int dj = ((j & 3) + tx * 4) + ((j >> 2) << 6);
            dmsk[j] = g_dmask[jb + dj];
        }
        __syncthreads();

        float acc[8][8];
        #pragma unroll
        for (int i = 0; i < 8; ++i)
            #pragma unroll
            for (int j = 0; j < 8; ++j) acc[i][j] = 0.f;

        const float4* A4 = (const float4*)sA;
        const float4* M4 = (const float4*)sMa;
        const float4* B4 = (const float4*)sB;
        const float4* N4 = (const float4*)sMb;

        #pragma unroll 2
        for (int d = 0; d < 64; ++d) {
            float a[8], ma[8], b[8], mb[8];
            float4 t0, t1;
            t0 = A4[d * 32 + ty];      t1 = A4[d * 32 + 16 + ty];
            a[0]=t0.x; a[1]=t0.y; a[2]=t0.z; a[3]=t0.w;
            a[4]=t1.x; a[5]=t1.y; a[6]=t1.z; a[7]=t1.w;
            t0 = M4[d * 32 + ty];      t1 = M4[d * 32 + 16 + ty];
            ma[0]=t0.x; ma[1]=t0.y; ma[2]=t0.z; ma[3]=t0.w;
            ma[4]=t1.x; ma[5]=t1.y; ma[6]=t1.z; ma[7]=t1.w;
            t0 = B4[d * 32 + tx];      t1 = B4[d * 32 + 16 + tx];
            b[0]=t0.x; b[1]=t0.y; b[2]=t0.z; b[3]=t0.w;
            b[4]=t1.x; b[5]=t1.y; b[6]=t1.z; b[7]=t1.w;
            t0 = N4[d * 32 + tx];      t1 = N4[d * 32 + 16 + tx];
            mb[0]=t0.x; mb[1]=t0.y; mb[2]=t0.z; mb[3]=t0.w;
            mb[4]=t1.x; mb[5]=t1.y; mb[6]=t1.z; mb[7]=t1.w;

            float a2[8], am[8], b2[8];
            #pragma unroll
            for (int i = 0; i < 8; ++i) { a2[i] = a[i] * a[i]; am[i] = -2.f * a[i]; }
            #pragma unroll
            for (int j = 0; j < 8; ++j) { b2[j] = b[j] * b[j]; }
            #pragma unroll
            for (int i = 0; i < 8; ++i)
                #pragma unroll
                for (int j = 0; j < 8; ++j) {
                    float s = acc[i][j];
                    s = fmaf(a2[i], mb[j], s);   // Σ a² · obs_b
                    s = fmaf(ma[i], b2[j], s);   // Σ obs_a · b²
                    s = fmaf(am[i],  b[j], s);   // − 2 Σ a·b
                    acc[i][j] = s;
                }
        }
        __syncthreads();   // everyone done reading sB/sMb; safe to alias sDist

        // keys: (clip(d2,0)/present)*64 in the reference's fp32 op order
        #pragma unroll
        for (int i = 0; i < 8; ++i) {
            int qi = ((i & 3) + ty * 4) + ((i >> 2) << 6);
            #pragma unroll
            for (int j = 0; j < 8; ++j) {
                int dj = ((j & 3) + tx * 4) + ((j >> 2) << 6);
                int p = __popcll(qm[i] & dmsk[j]);
                float key = (p > 0) ? (fmaxf(acc[i][j], 0.f) / (float)p) * 64.f : INFF;
                sDist[qi * 128 + dj] = key;
            }
        }
        __syncthreads();

        // per-query top-32 (unsorted list + tracked max; index-aware eviction)
        if (tid < 128) {
            const int base = tid * NC;
            for (int j = 0; j < 128; ++j) {
                float v = sDist[tid * 128 + j];
                if (v < curMax) {
                    sKey[base + curPos] = v;
                    sIdx[base + curPos] = jb + j;
                    float m = -INFF; int mp = 0; int mi = -1;
                    #pragma unroll
                    for (int k = 0; k < NC; ++k) {
                        float kk = sKey[base + k];
                        int   ii = sIdx[base + k];
                        if (kk > m || (kk == m && ii > mi)) { m = kk; mp = k; mi = ii; }
                    }
                    curMax = m; curPos = mp;
                }
            }
        }
        __syncthreads();   // selection done reading sDist before next tile load
    }

    // final sort by (key asc, idx asc) + writeout
    if (tid < 128) {
        const int base = tid * NC;
        for (int a = 1; a < NC; ++a) {
            float k = sKey[base + a]; int ix = sIdx[base + a];
            int b = a - 1;
            while (b >= 0) {
                float kb = sKey[base + b]; int ib = sIdx[base + b];
                if (kb > k || (kb == k && ib > ix)) {
                    sKey[base + b + 1] = kb; sIdx[base + b + 1] = ib; --b;
                } else break;
            }
            sKey[base + b + 1] = k; sIdx[base + b + 1] = ix;
        }
        int q = q0 + tid;
        for (int k = 0; k < NC; ++k) {
            g_ckey[q * NC + k] = sKey[base + k];
            g_cidx[q * NC + k] = sIdx[base + k];
        }
    }
}

// ---------------- kernel 3: per-missing-column imputation ----------------
__global__ void impute_kernel(const float* __restrict__ X, const float* __restrict__ F,
                              float* __restrict__ out) {
    int warp = (blockIdx.x * blockDim.x + threadIdx.x) >> 5;
    int lane = threadIdx.x & 31;
    if (warp >= NQ) return;
    const int q = warp;

    float ck = g_ckey[q * NC + lane];
    int   ci = g_cidx[q * NC + lane];
    bool cfin = (ck < INFF);
    unsigned long long dm = 0ull;
    if (cfin) dm = g_dmask[ci];

    float x0 = X[q * 64 + lane], x1 = X[q * 64 + 32 + lane];
    float o0 = x0, o1 = x1;

    unsigned long long miss = ~g_qmask[q];
    while (miss) {
        int c = __ffsll((long long)miss) - 1;
        miss &= miss - 1;
        bool ok = cfin && ((dm >> c) & 1ull);
        float v = ok ? F[ci * 64 + c] : 0.f;
        unsigned m = __ballot_sync(0xffffffffu, ok);
        unsigned sel = 0; int cnt = 0;
        #pragma unroll
        for (int k = 0; k < KNN; ++k) {
            unsigned bb = m & (0u - m);
            sel |= bb; m ^= bb; cnt += (bb != 0u);
        }
        float contrib = ((sel >> lane) & 1u) ? v : 0.f;
        #pragma unroll
        for (int off = 16; off > 0; off >>= 1)
            contrib += __shfl_xor_sync(0xffffffffu, contrib, off);
        float imput = (cnt > 0) ? (contrib / (float)cnt) : g_colmean[c];
        if (lane == (c & 31)) { if (c < 32) o0 = imput; else o1 = imput; }
    }
    out[q * 64 + lane]      = o0;
    out[q * 64 + 32 + lane] = o1;
}

// ---------------- launch ----------------
extern "C" void kernel_launch(void* const* d_in, const int* in_sizes, int n_in,
                              void* d_out, int out_size) {
    const float* X = (const float*)d_in[0];
    const float* F = (const float*)d_in[1];
    float* out = (float*)d_out;

    masks_kernel<<<(NQ + NF) / 8, 256>>>(X, F);
    colmean_kernel<<<DD, 256>>>(F);

    const int smem = 40960 * (int)sizeof(float);   // 163840 B
    cudaFuncSetAttribute(dist_topk_kernel, cudaFuncAttributeMaxDynamicSharedMemorySize, smem);
    dist_topk_kernel<<<NQ / 128, 256, smem>>>(X, F);

    impute_kernel<<<NQ / 8, 256>>>(X, F, out);
}

// round 3
// speedup vs baseline: 1.0798x; 1.0798x over previous
#include <cuda_runtime.h>

#define NQ 16384
#define NF 8192
#define DD 64
#define KNN 5
#define NC 32
#define NDIM 192   // augmented dims = 3 * DD

#define INFF __int_as_float(0x7f800000)

// ---------------- device scratch (static, no allocation) ----------------
__device__ unsigned long long g_qmask[NQ];   // bit c = 1 if X[q,c] observed
__device__ unsigned long long g_dmask[NF];   // bit c = 1 if fit[j,c] observed
__device__ float g_colmean[DD];
__device__ float g_ckey[NQ * NC];
__device__ int   g_cidx[NQ * NC];
__device__ float g_AaugT[NDIM * NQ];         // dim-major: [t][q]
__device__ float g_BaugT[NDIM * NF];         // dim-major: [t][j]

__device__ __forceinline__ bool obs_f(float v) {
    return (__float_as_uint(v) & 0x7fffffffu) <= 0x7f800000u;
}

#define FMA2(acc, a, b) asm("fma.rn.f32x2 %0, %1, %2, %0;" : "+l"(acc) : "l"(a), "l"(b))

// ---------------- kernel 0: observation bitmasks -------------------------
__global__ void masks_kernel(const float* __restrict__ X, const float* __restrict__ F) {
    int row  = blockIdx.x * 8 + (threadIdx.x >> 5);
    int lane = threadIdx.x & 31;
    const float* p;
    unsigned long long* o;
    int r;
    if (row < NQ)            { p = X; o = g_qmask; r = row; }
    else if (row < NQ + NF)  { p = F; o = g_dmask; r = row - NQ; }
    else return;
    float v0 = p[r * 64 + lane];
    float v1 = p[r * 64 + 32 + lane];
    unsigned lo = __ballot_sync(0xffffffffu, obs_f(v0));
    unsigned hi = __ballot_sync(0xffffffffu, obs_f(v1));
    if (lane == 0) o[r] = (unsigned long long)lo | ((unsigned long long)hi << 32);
}

// ---------------- kernel 1: per-column means of fit ----------------------
__global__ void colmean_kernel(const float* __restrict__ F) {
    int c = blockIdx.x;
    float s = 0.f, n = 0.f;
    for (int r = threadIdx.x; r < NF; r += blockDim.x) {
        float v = F[r * 64 + c];
        if (obs_f(v)) { s += v; n += 1.f; }
    }
    __shared__ float ss[256], sn[256];
    ss[threadIdx.x] = s; sn[threadIdx.x] = n;
    __syncthreads();
    for (int st = 128; st > 0; st >>= 1) {
        if (threadIdx.x < st) {
            ss[threadIdx.x] += ss[threadIdx.x + st];
            sn[threadIdx.x] += sn[threadIdx.x + st];
        }
        __syncthreads();
    }
    if (threadIdx.x == 0) g_colmean[c] = ss[0] / fmaxf(sn[0], 1.f);
}

// ---------------- kernel 1b: build augmented, transposed matrices --------
// A' = {a^2, a, ma}, B' = {mb, -2b, b^2}  so  d2 = A' . B'^T (same 3 terms/dim)
__global__ void aug_kernel(const float* __restrict__ X, const float* __restrict__ F) {
    __shared__ float s[64][65];
    int b = blockIdx.x;
    const float* src; float* dst; int r0, stride; bool isA;
    if (b < NQ / 64) { src = X; dst = g_AaugT; r0 = b * 64; stride = NQ; isA = true; }
    else             { src = F; dst = g_BaugT; r0 = (b - NQ / 64) * 64; stride = NF; isA = false; }
    int tid = threadIdx.x;
    for (int i = tid; i < 4096; i += 256) {
        int r = i >> 6, c = i & 63;
        s[r][c] = src[(r0 + r) * 64 + c];
    }
    __syncthreads();
    for (int i = tid; i < NDIM * 64; i += 256) {
        int t = i >> 6, rl = i & 63;
        int d = (t * 171) >> 9;        // t / 3 for t < 192
        int kind = t - 3 * d;
        float v = s[rl][d];
        bool ob = obs_f(v);
        float vc = ob ? v : 0.f;
        float out;
        if (isA) out = (kind == 0) ? vc * vc : (kind == 1) ? vc : (ob ? 1.f : 0.f);
        else     out = (kind == 0) ? (ob ? 1.f : 0.f) : (kind == 1) ? -2.f * vc : vc * vc;
        dst[t * stride + r0 + rl] = out;
    }
}

// ---------------- kernel 2: packed-FMA distances + global top-32 ---------
// CTA: 128 queries x all 8192 donors (128 subtiles of 64). 256 threads.
// Thread tile: 8 queries x 4 donors, computed with f32x2 FFMA2.
// smem layout (floats):
//   sA   [0      , 24576)  : A' tile, dim-major [192][128]
//   sB   [24576  , 49152)  : B' subtile, duplicated pairs [192][128]
//   sDist aliases sB       : [128][65] padded keys
//   sKey [49152  , 53376)  : [128][33] padded
//   sIdx [53376  , 57600)  : [128][33] padded
//   sInv [57600  , 57665)
#define SMEM_FLOATS 57665

__global__ __launch_bounds__(256) void dist_topk_kernel() {
    extern __shared__ float sm[];
    float* sA    = sm;
    float* sB    = sm + 24576;
    float* sDist = sB;
    float* sKey  = sm + 49152;
    int*   sIdx  = (int*)(sm + 53376);
    float* sInv  = sm + 57600;

    const int tid = threadIdx.x;
    const int tx = tid & 15, ty = tid >> 4;
    const int q0 = blockIdx.x * 128;

    if (tid <= 64) sInv[tid] = tid ? 1.0f / (float)tid : 1.0f;

    // load A' tile (dim-major, coalesced float4 copy)
    {
        float4* dA = (float4*)sA;
        const float4* srcA = (const float4*)g_AaugT;
        for (int i = tid; i < 6144; i += 256) {
            int t = i >> 5, w = i & 31;
            dA[i] = srcA[t * (NQ / 4) + (q0 >> 2) + w];
        }
    }
    if (tid < 128) {
        #pragma unroll
        for (int k = 0; k < NC; ++k) {
            sKey[tid * 33 + k] = INFF;
            sIdx[tid * 33 + k] = 0x7fffffff;
        }
    }
    unsigned long long qm[8];
    #pragma unroll
    for (int i = 0; i < 8; ++i) qm[i] = g_qmask[q0 + ty * 8 + i];
    float curMax = INFF; int curPos = 0;
    __syncthreads();

    for (int t = 0; t < 128; ++t) {
        const int jb = t * 64;
        // fill duplicated B' subtile: for j-group g=j>>4, wi=j&15:
        //   dst = dim*128 + (g>>1)*64 + wi*4 + (g&1)*2, written twice (float2 {v,v})
        for (int i = tid; i < NDIM * 64; i += 256) {
            int dm = i >> 6, j = i & 63;
            float v = g_BaugT[dm * NF + jb + j];
            int g = j >> 4, wi = j & 15;
            int dst = dm * 128 + ((g >> 1) << 6) + (wi << 2) + ((g & 1) << 1);
            ((float2*)sB)[dst >> 1] = make_float2(v, v);
        }
        unsigned long long dmk[4];
        dmk[0] = g_dmask[jb + tx];
        dmk[1] = g_dmask[jb + tx + 16];
        dmk[2] = g_dmask[jb + tx + 32];
        dmk[3] = g_dmask[jb + tx + 48];
        __syncthreads();

        unsigned long long acc[4][4];
        #pragma unroll
        for (int i = 0; i < 4; ++i)
            #pragma unroll
            for (int j = 0; j < 4; ++j) acc[i][j] = 0ull;

        const ulonglong2* A2 = (const ulonglong2*)sA;   // 16B units; row = 32 units
        const ulonglong2* B2 = (const ulonglong2*)sB;

        #pragma unroll 4
        for (int d = 0; d < NDIM; ++d) {
            ulonglong2 av0 = A2[d * 32 + ty * 2];       // {a0,a1},{a2,a3}
            ulonglong2 av1 = A2[d * 32 + ty * 2 + 1];   // {a4,a5},{a6,a7}
            ulonglong2 bv0 = B2[d * 32 + tx];           // {b_tx,b_tx},{b_tx16,b_tx16}
            ulonglong2 bv1 = B2[d * 32 + 16 + tx];      // {b_tx32,..},{b_tx48,..}
            FMA2(acc[0][0], av0.x, bv0.x); FMA2(acc[0][1], av0.x, bv0.y);
            FMA2(acc[0][2], av0.x, bv1.x); FMA2(acc[0][3], av0.x, bv1.y);
            FMA2(acc[1][0], av0.y, bv0.x); FMA2(acc[1][1], av0.y, bv0.y);
            FMA2(acc[1][2], av0.y, bv1.x); FMA2(acc[1][3], av0.y, bv1.y);
            FMA2(acc[2][0], av1.x, bv0.x); FMA2(acc[2][1], av1.x, bv0.y);
            FMA2(acc[2][2], av1.x, bv1.x); FMA2(acc[2][3], av1.x, bv1.y);
            FMA2(acc[3][0], av1.y, bv0.x); FMA2(acc[3][1], av1.y, bv0.y);
            FMA2(acc[3][2], av1.y, bv1.x); FMA2(acc[3][3], av1.y, bv1.y);
        }
        __syncthreads();   // done reading sB; safe to alias sDist

        // keys: (clip(d2,0)/present)*64 via exact-reciprocal table
        #pragma unroll
        for (int ip = 0; ip < 4; ++ip) {
            #pragma unroll
            for (int jd = 0; jd < 4; ++jd) {
                unsigned lo = (unsigned)(acc[ip][jd] & 0xffffffffull);
                unsigned hi = (unsigned)(acc[ip][jd] >> 32);
                int jl = tx + (jd << 4);
                #pragma unroll
                for (int h = 0; h < 2; ++h) {
                    float f = __uint_as_float(h ? hi : lo);
                    int ql = ty * 8 + ip * 2 + h;
                    int p = __popcll(qm[ip * 2 + h] & dmk[jd]);
                    float key = (p > 0) ? fmaxf(f, 0.f) * sInv[p] * 64.f : INFF;
                    sDist[ql * 65 + jl] = key;
                }
            }
        }
        __syncthreads();

        // per-query top-32 (conflict-free padded rows)
        if (tid < 128) {
            const int base = tid * 33;
            const float* row = sDist + tid * 65;
            for (int j = 0; j < 64; ++j) {
                float v = row[j];
                if (v < curMax) {
                    sKey[base + curPos] = v;
                    sIdx[base + curPos] = jb + j;
                    float m = -INFF; int mp = 0; int mi = -1;
                    #pragma unroll
                    for (int k = 0; k < NC; ++k) {
                        float kk = sKey[base + k];
                        int   ii = sIdx[base + k];
                        if (kk > m || (kk == m && ii > mi)) { m = kk; mp = k; mi = ii; }
                    }
                    curMax = m; curPos = mp;
                }
            }
        }
        __syncthreads();
    }

    // final sort by (key asc, idx asc) + writeout
    if (tid < 128) {
        const int base = tid * 33;
        for (int a = 1; a < NC; ++a) {
            float k = sKey[base + a]; int ix = sIdx[base + a];
            int b = a - 1;
            while (b >= 0) {
                float kb = sKey[base + b]; int ib = sIdx[base + b];
                if (kb > k || (kb == k && ib > ix)) {
                    sKey[base + b + 1] = kb; sIdx[base + b + 1] = ib; --b;
                } else break;
            }
            sKey[base + b + 1] = k; sIdx[base + b + 1] = ix;
        }
        int q = q0 + tid;
        for (int k = 0; k < NC; ++k) {
            g_ckey[q * NC + k] = sKey[base + k];
            g_cidx[q * NC + k] = sIdx[base + k];
        }
    }
}

// ---------------- kernel 3: per-missing-column imputation ----------------
__global__ void impute_kernel(const float* __restrict__ X, const float* __restrict__ F,
                              float* __restrict__ out) {
    int warp = (blockIdx.x * blockDim.x + threadIdx.x) >> 5;
    int lane = threadIdx.x & 31;
    if (warp >= NQ) return;
    const int q = warp;

    float ck = g_ckey[q * NC + lane];
    int   ci = g_cidx[q * NC + lane];
    bool cfin = (ck < INFF);
    unsigned long long dm = 0ull;
    if (cfin) dm = g_dmask[ci];

    float x0 = X[q * 64 + lane], x1 = X[q * 64 + 32 + lane];
    float o0 = x0, o1 = x1;

    unsigned long long miss = ~g_qmask[q];
    while (miss) {
        int c = __ffsll((long long)miss) - 1;
        miss &= miss - 1;
        bool ok = cfin && ((dm >> c) & 1ull);
        float v = ok ? F[ci * 64 + c] : 0.f;
        unsigned m = __ballot_sync(0xffffffffu, ok);
        unsigned sel = 0; int cnt = 0;
        #pragma unroll
        for (int k = 0; k < KNN; ++k) {
            unsigned bb = m & (0u - m);
            sel |= bb; m ^= bb; cnt += (bb != 0u);
        }
        float contrib = ((sel >> lane) & 1u) ? v : 0.f;
        #pragma unroll
        for (int off = 16; off > 0; off >>= 1)
            contrib += __shfl_xor_sync(0xffffffffu, contrib, off);
        float imput = (cnt > 0) ? (contrib / (float)cnt) : g_colmean[c];
        if (lane == (c & 31)) { if (c < 32) o0 = imput; else o1 = imput; }
    }
    out[q * 64 + lane]      = o0;
    out[q * 64 + 32 + lane] = o1;
}

// ---------------- launch ----------------
extern "C" void kernel_launch(void* const* d_in, const int* in_sizes, int n_in,
                              void* d_out, int out_size) {
    const float* X = (const float*)d_in[0];
    const float* F = (const float*)d_in[1];
    float* out = (float*)d_out;

    masks_kernel<<<(NQ + NF) / 8, 256>>>(X, F);
    colmean_kernel<<<DD, 256>>>(F);
    aug_kernel<<<(NQ + NF) / 64, 256>>>(X, F);

    const int smem = SMEM_FLOATS * (int)sizeof(float);   // 230660 B
    cudaFuncSetAttribute(dist_topk_kernel, cudaFuncAttributeMaxDynamicSharedMemorySize, smem);
    dist_topk_kernel<<<NQ / 128, 256, smem>>>();

    impute_kernel<<<NQ / 8, 256>>>(X, F, out);
}

// round 12
// speedup vs baseline: 2.3459x; 2.1725x over previous
#include <cuda_runtime.h>
#include <cuda_bf16.h>
#include <mma.h>
#include <cstdint>

using namespace nvcuda;

#define NQ 16384
#define NF 8192
#define KNN 5
#define NC 32
#define NCAND 64
#define KA 192
#define DT 32            // donors per tile
#define NT (NF / DT)     // 256 tiles
#define LDB 200          // bf16 element stride for sA/sB rows
#define LDC 36           // f32 element stride for sKeys

#define INFF __int_as_float(0x7f800000)

// smem byte offsets
#define OFF_SA    0                     // 128*200*2   = 51200
#define OFF_SB    51200                 // 2*32*200*2  = 25600
#define OFF_KEYS  76800                 // 128*36*4    = 18432
#define OFF_KEYL  95232                 // 64*128*4    = 32768
#define OFF_IDXL  128000                // 64*128*4    = 32768
#define OFF_DM    160768                // 2*32*8      = 512
#define OFF_INV   161280                // 65*4
#define SMEM_P1   161568

__device__ unsigned long long g_qmask[NQ];
__device__ unsigned long long g_dmask[NF];
__device__ float g_colmean[64];
__device__ float g_ckey[NQ * NC];
__device__ int   g_cidx[NQ * NC];
__device__ int   g_cand[NQ * NCAND];
__device__ __nv_bfloat16 g_AB16[(size_t)NQ * KA];
__device__ __nv_bfloat16 g_BB16[(size_t)NF * KA];

__device__ __forceinline__ bool obs_f(float v) {
    return (__float_as_uint(v) & 0x7fffffffu) <= 0x7f800000u;
}
__device__ __forceinline__ uint32_t s2u(const void* p) {
    return (uint32_t)__cvta_generic_to_shared(p);
}
#define CPASYNC16(d, s) asm volatile("cp.async.cg.shared.global [%0], [%1], 16;" :: "r"(d), "l"(s))
#define CPCOMMIT() asm volatile("cp.async.commit_group;" ::: "memory")
#define CPWAIT0()  asm volatile("cp.async.wait_group 0;" ::: "memory")

// ---------------- prep kernels ----------------
__global__ void masks_kernel(const float* __restrict__ X, const float* __restrict__ F) {
    int row = blockIdx.x * 8 + (threadIdx.x >> 5);
    int lane = threadIdx.x & 31;
    const float* p; unsigned long long* o; int r;
    if (row < NQ)           { p = X; o = g_qmask; r = row; }
    else if (row < NQ + NF) { p = F; o = g_dmask; r = row - NQ; }
    else return;
    unsigned lo = __ballot_sync(0xffffffffu, obs_f(p[r * 64 + lane]));
    unsigned hi = __ballot_sync(0xffffffffu, obs_f(p[r * 64 + 32 + lane]));
    if (lane == 0) o[r] = (unsigned long long)lo | ((unsigned long long)hi << 32);
}

__global__ void colmean_kernel(const float* __restrict__ F) {
    int c = blockIdx.x;
    float s = 0.f, n = 0.f;
    for (int r = threadIdx.x; r < NF; r += 256) {
        float v = F[r * 64 + c];
        if (obs_f(v)) { s += v; n += 1.f; }
    }
    __shared__ float ss[256], sn[256];
    ss[threadIdx.x] = s; sn[threadIdx.x] = n;
    __syncthreads();
    for (int st = 128; st > 0; st >>= 1) {
        if (threadIdx.x < st) {
            ss[threadIdx.x] += ss[threadIdx.x + st];
            sn[threadIdx.x] += sn[threadIdx.x + st];
        }
        __syncthreads();
    }
    if (threadIdx.x == 0) g_colmean[c] = ss[0] / fmaxf(sn[0], 1.f);
}

// A' = {a^2, -2a, ma}, B' = {mb, b, b^2} so sum_t A'B' = masked d^2
__global__ void augb16_kernel(const float* __restrict__ X, const float* __restrict__ F) {
    int i = blockIdx.x * 256 + threadIdx.x;
    if (i >= (NQ + NF) * 64) return;
    int row = i >> 6, d = i & 63;
    if (row < NQ) {
        float v = X[row * 64 + d];
        bool ob = obs_f(v); float vc = ob ? v : 0.f;
        __nv_bfloat16* o = g_AB16 + (size_t)row * KA + 3 * d;
        o[0] = __float2bfloat16(vc * vc);
        o[1] = __float2bfloat16(-2.f * vc);
        o[2] = __float2bfloat16(ob ? 1.f : 0.f);
    } else {
        row -= NQ;
        float v = F[row * 64 + d];
        bool ob = obs_f(v); float vc = ob ? v : 0.f;
        __nv_bfloat16* o = g_BB16 + (size_t)row * KA + 3 * d;
        o[0] = __float2bfloat16(ob ? 1.f : 0.f);
        o[1] = __float2bfloat16(vc);
        o[2] = __float2bfloat16(vc * vc);
    }
}

// ---------------- phase 1: wmma bf16 approx d^2 + top-64 candidates ------
__device__ __forceinline__ void loadB_tile(char* smem, int stage, int tile, int tid) {
    uint32_t sbB = s2u(smem) + OFF_SB + stage * 12800;
    for (int i = tid; i < DT * 24; i += 512) {
        int r = i / 24, c = i % 24;
        CPASYNC16(sbB + r * 400 + c * 16,
                  (const char*)g_BB16 + (((size_t)tile * DT + r) * KA + c * 8) * 2);
    }
    if (tid < 16) {
        uint32_t sbD = s2u(smem) + OFF_DM + stage * 256 + tid * 16;
        CPASYNC16(sbD, (const char*)g_dmask + ((size_t)tile * DT + tid * 2) * 8);
    }
}

__device__ __forceinline__ void cand_push(float key, int idx, float* sKeyL, int* sIdxL,
                                          float* gmax, float& curMax, int q) {
    float m = gmax[0]; int g = 0;
    #pragma unroll
    for (int h = 1; h < 8; ++h) if (gmax[h] > m) { m = gmax[h]; g = h; }
    int pos = g * 8; float mv = sKeyL[(g * 8) * 128 + q];
    #pragma unroll
    for (int e = 1; e < 8; ++e) {
        float v = sKeyL[(g * 8 + e) * 128 + q];
        if (v > mv) { mv = v; pos = g * 8 + e; }
    }
    sKeyL[pos * 128 + q] = key;
    sIdxL[pos * 128 + q] = idx;
    float ng = -INFF;
    #pragma unroll
    for (int e = 0; e < 8; ++e) ng = fmaxf(ng, sKeyL[(g * 8 + e) * 128 + q]);
    gmax[g] = ng;
    curMax = gmax[0];
    #pragma unroll
    for (int h = 1; h < 8; ++h) curMax = fmaxf(curMax, gmax[h]);
}

__global__ __launch_bounds__(512) void phase1_kernel() {
    extern __shared__ char smem[];
    __nv_bfloat16* sA = (__nv_bfloat16*)(smem + OFF_SA);
    float* sKeys = (float*)(smem + OFF_KEYS);
    float* sKeyL = (float*)(smem + OFF_KEYL);
    int*   sIdxL = (int*)(smem + OFF_IDXL);
    float* sInv  = (float*)(smem + OFF_INV);

    const int tid = threadIdx.x;
    const int wid = tid >> 5;
    const int wr = wid >> 1, wc = wid & 1;
    const int q0 = blockIdx.x * 128;

    if (tid <= 64) sInv[tid] = tid ? 1.0f / (float)tid : 1.0f;
    for (int i = tid; i < 8192; i += 512) { sKeyL[i] = INFF; sIdxL[i] = 0x7fffffff; }

    // load A' tile: 128 rows x 192 bf16, row stride LDB
    for (int i = tid; i < 128 * 24; i += 512) {
        int r = i / 24, c = i % 24;
        *(uint4*)(sA + r * LDB + c * 8) =
            *(const uint4*)(g_AB16 + ((size_t)(q0 + r)) * KA + c * 8);
    }
    loadB_tile(smem, 0, 0, tid);
    CPCOMMIT(); CPWAIT0();
    __syncthreads();

    // preload A fragments (12 k-steps), register-resident
    wmma::fragment<wmma::matrix_a, 16, 16, 16, __nv_bfloat16, wmma::row_major> afr[12];
    #pragma unroll
    for (int k = 0; k < 12; ++k)
        wmma::load_matrix_sync(afr[k], sA + wr * 16 * LDB + k * 16, LDB);

    unsigned long long qm = (tid < 128) ? g_qmask[q0 + tid] : 0ull;
    float curMax = INFF;
    float gmax[8];
    #pragma unroll
    for (int h = 0; h < 8; ++h) gmax[h] = INFF;

    for (int t = 0; t < NT; ++t) {
        int st = t & 1;
        if (t < NT - 1) { loadB_tile(smem, st ^ 1, t + 1, tid); CPCOMMIT(); }

        // MMA: 16 warps x (16q x 16donor), K = 192
        {
            const __nv_bfloat16* bbase =
                (const __nv_bfloat16*)(smem + OFF_SB + st * 12800) + wc * 16 * LDB;
            wmma::fragment<wmma::accumulator, 16, 16, 16, float> cfr;
            wmma::fill_fragment(cfr, 0.0f);
            #pragma unroll
            for (int k = 0; k < 12; ++k) {
                wmma::fragment<wmma::matrix_b, 16, 16, 16, __nv_bfloat16, wmma::col_major> bfr;
                wmma::load_matrix_sync(bfr, bbase + k * 16, LDB);
                wmma::mma_sync(cfr, afr[k], bfr, cfr);
            }
            wmma::store_matrix_sync(sKeys + wr * 16 * LDC + wc * 16, cfr, LDC,
                                    wmma::mem_row_major);
        }
        __syncthreads();

        // selection: 128 threads, one query each
        if (tid < 128) {
            const unsigned long long* dmp =
                (const unsigned long long*)(smem + OFF_DM + st * 256);
            int jb = t * DT;
            const float* row = sKeys + tid * LDC;
            for (int j = 0; j < DT; ++j) {
                int p = __popcll(qm & dmp[j]);
                float key = fmaxf(row[j], 0.f) * sInv[p];
                if (p > 0 && key < curMax)
                    cand_push(key, jb + j, sKeyL, sIdxL, gmax, curMax, tid);
            }
        }
        __syncthreads();
        if (t < NT - 1) { CPWAIT0(); __syncthreads(); }
    }

    if (tid < 128) {
        #pragma unroll
        for (int i = 0; i < NCAND; ++i)
            g_cand[(size_t)(q0 + tid) * NCAND + i] = sIdxL[i * 128 + tid];
    }
}

// ---------------- phase 2: exact fp32 rescore + exact top-32 -------------
__global__ __launch_bounds__(256) void phase2_kernel(const float* __restrict__ X,
                                                     const float* __restrict__ F) {
    __shared__ float sx[4][64];
    __shared__ unsigned long long sqm[4];
    __shared__ float sk[4][64];
    __shared__ int   si[4][64];
    int ql = threadIdx.x >> 6, ci = threadIdx.x & 63;
    int q = blockIdx.x * 4 + ql;
    sx[ql][ci] = X[q * 64 + ci];
    if (ci == 0) sqm[ql] = g_qmask[q];
    __syncthreads();

    int cand = g_cand[(size_t)q * NCAND + ci];
    float key = INFF;
    if ((unsigned)cand < NF) {
        unsigned long long dm = g_dmask[cand];
        unsigned long long qmv = sqm[ql];
        const float4* frow = (const float4*)(F + (size_t)cand * 64);
        float acc = 0.f;
        #pragma unroll
        for (int d4 = 0; d4 < 16; ++d4) {
            float4 bq = frow[d4];
            float bb[4] = {bq.x, bq.y, bq.z, bq.w};
            #pragma unroll
            for (int e = 0; e < 4; ++e) {
                int d = d4 * 4 + e;
                float mbf = ((dm  >> d) & 1ull) ? 1.f : 0.f;
                float maf = ((qmv >> d) & 1ull) ? 1.f : 0.f;
                float a = (maf != 0.f) ? sx[ql][d] : 0.f;
                float b = (mbf != 0.f) ? bb[e] : 0.f;
                acc = fmaf(a * a, mbf, acc);
                acc = fmaf(maf, b * b, acc);
                acc = fmaf(-2.f * a, b, acc);
            }
        }
        int p = __popcll(qmv & dm);
        if (p > 0) key = fmaxf(acc, 0.f) * (1.0f / (float)p) * 64.f;
    } else cand = 0x7fffffff;
    sk[ql][ci] = key; si[ql][ci] = cand;
    __syncthreads();

    // exact rank by (key asc, idx asc, slot asc) -> scatter sorted top-32
    int rank = 0;
    for (int e = 0; e < 64; ++e) {
        float k2 = sk[ql][e]; int i2 = si[ql][e];
        bool less = (k2 < key) || (k2 == key && (i2 < cand || (i2 == cand && e < ci)));
        rank += less ? 1 : 0;
    }
    if (rank < NC) {
        g_ckey[(size_t)q * NC + rank] = key;
        g_cidx[(size_t)q * NC + rank] = cand;
    }
}

// ---------------- impute (verified R1) ------------------------------------
__global__ void impute_kernel(const float* __restrict__ X, const float* __restrict__ F,
                              float* __restrict__ out) {
    int warp = (blockIdx.x * blockDim.x + threadIdx.x) >> 5;
    int lane = threadIdx.x & 31;
    if (warp >= NQ) return;
    const int q = warp;

    float ck = g_ckey[q * NC + lane];
    int   ci = g_cidx[q * NC + lane];
    bool cfin = (ck < INFF);
    unsigned long long dm = 0ull;
    if (cfin) dm = g_dmask[ci];

    float x0 = X[q * 64 + lane], x1 = X[q * 64 + 32 + lane];
    float o0 = x0, o1 = x1;

    unsigned long long miss = ~g_qmask[q];
    while (miss) {
        int c = __ffsll((long long)miss) - 1;
        miss &= miss - 1;
        bool ok = cfin && ((dm >> c) & 1ull);
        float v = ok ? F[ci * 64 + c] : 0.f;
        unsigned m = __ballot_sync(0xffffffffu, ok);
        unsigned sel = 0; int cnt = 0;
        #pragma unroll
        for (int k = 0; k < KNN; ++k) {
            unsigned bb = m & (0u - m);
            sel |= bb; m ^= bb; cnt += (bb != 0u);
        }
        float contrib = ((sel >> lane) & 1u) ? v : 0.f;
        #pragma unroll
        for (int off = 16; off > 0; off >>= 1)
            contrib += __shfl_xor_sync(0xffffffffu, contrib, off);
        float imput = (cnt > 0) ? (contrib / (float)cnt) : g_colmean[c];
        if (lane == (c & 31)) { if (c < 32) o0 = imput; else o1 = imput; }
    }
    out[q * 64 + lane]      = o0;
    out[q * 64 + 32 + lane] = o1;
}

// ---------------- launch ----------------
extern "C" void kernel_launch(void* const* d_in, const int* in_sizes, int n_in,
                              void* d_out, int out_size) {
    const float* X = (const float*)d_in[0];
    const float* F = (const float*)d_in[1];
    float* out = (float*)d_out;

    masks_kernel<<<(NQ + NF) / 8, 256>>>(X, F);
    colmean_kernel<<<64, 256>>>(F);
    augb16_kernel<<<(NQ + NF) * 64 / 256, 256>>>(X, F);

    cudaFuncSetAttribute(phase1_kernel, cudaFuncAttributeMaxDynamicSharedMemorySize, SMEM_P1);
    phase1_kernel<<<NQ / 128, 512, SMEM_P1>>>();

    phase2_kernel<<<NQ / 4, 256>>>(X, F);
    impute_kernel<<<NQ / 8, 256>>>(X, F, out);
}

// round 15
// speedup vs baseline: 2.4658x; 1.0511x over previous
#include <cuda_runtime.h>
#include <cuda_bf16.h>
#include <mma.h>
#include <cstdint>

using namespace nvcuda;

#define NQ 16384
#define NF 8192
#define KNN 5
#define NC 32
#define NCAND 64
#define KA 192
#define DT 64            // donors per tile
#define NT (NF / DT)     // 128 tiles
#define LDB 200          // bf16 element stride for sA rows
#define LDBT 72          // bf16 element stride for sB rows (144B, conflict-stagger)
#define LDC 68           // f32 element stride for sKeys

#define INFF __int_as_float(0x7f800000)

// smem byte offsets
#define OFF_SA    0                     // 128*200*2      = 51200
#define OFF_SB    51200                 // 2*192*144      = 55296
#define OFF_KEYS  106496                // 128*68*4       = 34816
#define OFF_KEYL  141312                // 64*128*4       = 32768
#define OFF_IDXL  174080                // 64*128*4       = 32768
#define OFF_DM    206848                // 2*64*8         = 1024
#define OFF_INV   207872                // 65*4
#define SMEM_P1   208144

__device__ unsigned long long g_qmask[NQ];
__device__ unsigned long long g_dmask[NF];
__device__ float g_colmean[64];
__device__ float g_ckey[NQ * NC];
__device__ int   g_cidx[NQ * NC];
__device__ int   g_cand[NQ * NCAND];
__device__ __nv_bfloat16 g_AB16[(size_t)NQ * KA];    // row-major [q][192]
__device__ __nv_bfloat16 g_BB16T[(size_t)KA * NF];   // transposed [k][donor]

__device__ __forceinline__ bool obs_f(float v) {
    return (__float_as_uint(v) & 0x7fffffffu) <= 0x7f800000u;
}
__device__ __forceinline__ uint32_t s2u(const void* p) {
    return (uint32_t)__cvta_generic_to_shared(p);
}
#define CPASYNC16(d, s) asm volatile("cp.async.cg.shared.global [%0], [%1], 16;" :: "r"(d), "l"(s))
#define CPCOMMIT() asm volatile("cp.async.commit_group;" ::: "memory")
#define CPWAIT0()  asm volatile("cp.async.wait_group 0;" ::: "memory")

// ---------------- prep kernels ----------------
__global__ void masks_kernel(const float* __restrict__ X, const float* __restrict__ F) {
    int row = blockIdx.x * 8 + (threadIdx.x >> 5);
    int lane = threadIdx.x & 31;
    const float* p; unsigned long long* o; int r;
    if (row < NQ)           { p = X; o = g_qmask; r = row; }
    else if (row < NQ + NF) { p = F; o = g_dmask; r = row - NQ; }
    else return;
    unsigned lo = __ballot_sync(0xffffffffu, obs_f(p[r * 64 + lane]));
    unsigned hi = __ballot_sync(0xffffffffu, obs_f(p[r * 64 + 32 + lane]));
    if (lane == 0) o[r] = (unsigned long long)lo | ((unsigned long long)hi << 32);
}

__global__ void colmean_kernel(const float* __restrict__ F) {
    int c = blockIdx.x;
    float s = 0.f, n = 0.f;
    for (int r = threadIdx.x; r < NF; r += 256) {
        float v = F[r * 64 + c];
        if (obs_f(v)) { s += v; n += 1.f; }
    }
    __shared__ float ss[256], sn[256];
    ss[threadIdx.x] = s; sn[threadIdx.x] = n;
    __syncthreads();
    for (int st = 128; st > 0; st >>= 1) {
        if (threadIdx.x < st) {
            ss[threadIdx.x] += ss[threadIdx.x + st];
            sn[threadIdx.x] += sn[threadIdx.x + st];
        }
        __syncthreads();
    }
    if (threadIdx.x == 0) g_colmean[c] = ss[0] / fmaxf(sn[0], 1.f);
}

// A' rows = {a^2, -2a, ma}
__global__ void augA_kernel(const float* __restrict__ X) {
    int i = blockIdx.x * 256 + threadIdx.x;
    if (i >= NQ * 64) return;
    int row = i >> 6, d = i & 63;
    float v = X[row * 64 + d];
    bool ob = obs_f(v); float vc = ob ? v : 0.f;
    __nv_bfloat16* o = g_AB16 + (size_t)row * KA + 3 * d;
    o[0] = __float2bfloat16(vc * vc);
    o[1] = __float2bfloat16(-2.f * vc);
    o[2] = __float2bfloat16(ob ? 1.f : 0.f);
}

// B' transposed: rows 3d+{0,1,2} = {mb, b, b^2} over donors (coalesced writes)
__global__ void augBT_kernel(const float* __restrict__ F) {
    int i = blockIdx.x * 256 + threadIdx.x;
    if (i >= 64 * NF) return;
    int d = i >> 13, j = i & (NF - 1);
    float v = F[(size_t)j * 64 + d];
    bool ob = obs_f(v); float vc = ob ? v : 0.f;
    g_BB16T[(size_t)(3 * d + 0) * NF + j] = __float2bfloat16(ob ? 1.f : 0.f);
    g_BB16T[(size_t)(3 * d + 1) * NF + j] = __float2bfloat16(vc);
    g_BB16T[(size_t)(3 * d + 2) * NF + j] = __float2bfloat16(vc * vc);
}

// ---------------- phase 1: wmma bf16 approx d^2 + top-64 candidates ------
__device__ __forceinline__ void loadB_tile(char* smem, int stage, int tile, int tid) {
    uint32_t sbB = s2u(smem) + OFF_SB + stage * 27648;
    #pragma unroll
    for (int i = tid; i < KA * 8; i += 512) {          // 192 rows x 8 chunks of 16B
        int r = i >> 3, c = i & 7;
        CPASYNC16(sbB + r * 144 + c * 16,
                  (const char*)g_BB16T + ((size_t)r * NF + (size_t)tile * DT) * 2 + c * 16);
    }
    if (tid < 32) {
        uint32_t sbD = s2u(smem) + OFF_DM + stage * 512 + tid * 16;
        CPASYNC16(sbD, (const char*)g_dmask + ((size_t)tile * DT) * 8 + tid * 16);
    }
}

__device__ __forceinline__ void cand_push(float key, int idx, float* sKeyL, int* sIdxL,
                                          float* gmax, float& curMax, int q) {
    float m = gmax[0]; int g = 0;
    #pragma unroll
    for (int h = 1; h < 8; ++h) if (gmax[h] > m) { m = gmax[h]; g = h; }
    int pos = g * 8; float mv = sKeyL[(g * 8) * 128 + q];
    #pragma unroll
    for (int e = 1; e < 8; ++e) {
        float v = sKeyL[(g * 8 + e) * 128 + q];
        if (v > mv) { mv = v; pos = g * 8 + e; }
    }
    sKeyL[pos * 128 + q] = key;
    sIdxL[pos * 128 + q] = idx;
    float ng = -INFF;
    #pragma unroll
    for (int e = 0; e < 8; ++e) ng = fmaxf(ng, sKeyL[(g * 8 + e) * 128 + q]);
    gmax[g] = ng;
    curMax = gmax[0];
    #pragma unroll
    for (int h = 1; h < 8; ++h) curMax = fmaxf(curMax, gmax[h]);
}

__global__ __launch_bounds__(512) void phase1_kernel() {
    extern __shared__ char smem[];
    __nv_bfloat16* sA = (__nv_bfloat16*)(smem + OFF_SA);
    float* sKeys = (float*)(smem + OFF_KEYS);
    float* sKeyL = (float*)(smem + OFF_KEYL);
    int*   sIdxL = (int*)(smem + OFF_IDXL);
    float* sInv  = (float*)(smem + OFF_INV);

    const int tid = threadIdx.x;
    const int wid = tid >> 5;
    const int wr = wid >> 1, wc = wid & 1;     // 8 m-tiles x 2 n-halves
    const int q0 = blockIdx.x * 128;

    if (tid <= 64) sInv[tid] = tid ? 1.0f / (float)tid : 1.0f;
    for (int i = tid; i < 8192; i += 512) { sKeyL[i] = INFF; sIdxL[i] = 0x7fffffff; }

    // load A' tile: 128 rows x 192 bf16, row stride LDB
    for (int i = tid; i < 128 * 24; i += 512) {
        int r = i / 24, c = i % 24;
        *(uint4*)(sA + r * LDB + c * 8) =
            *(const uint4*)(g_AB16 + ((size_t)(q0 + r)) * KA + c * 8);
    }
    loadB_tile(smem, 0, 0, tid);
    CPCOMMIT(); CPWAIT0();
    __syncthreads();

    // preload A fragments (12 k-steps), register-resident
    wmma::fragment<wmma::matrix_a, 16, 16, 16, __nv_bfloat16, wmma::row_major> afr[12];
    #pragma unroll
    for (int k = 0; k < 12; ++k)
        wmma::load_matrix_sync(afr[k], sA + wr * 16 * LDB + k * 16, LDB);

    unsigned long long qm = (tid < 128) ? g_qmask[q0 + tid] : 0ull;
    float curMax = INFF;
    float gmax[8];
    #pragma unroll
    for (int h = 0; h < 8; ++h) gmax[h] = INFF;

    for (int t = 0; t < NT; ++t) {
        int st = t & 1;
        if (t < NT - 1) { loadB_tile(smem, st ^ 1, t + 1, tid); CPCOMMIT(); }

        // MMA: each warp 16q x 32donor (2 independent accumulators), K = 192
        {
            const __nv_bfloat16* bbase =
                (const __nv_bfloat16*)(smem + OFF_SB + st * 27648) + wc * 32;
            wmma::fragment<wmma::accumulator, 16, 16, 16, float> c0, c1;
            wmma::fill_fragment(c0, 0.0f);
            wmma::fill_fragment(c1, 0.0f);
            #pragma unroll
            for (int k = 0; k < 12; ++k) {
                wmma::fragment<wmma::matrix_b, 16, 16, 16, __nv_bfloat16, wmma::row_major> b0, b1;
                wmma::load_matrix_sync(b0, bbase + k * 16 * LDBT, LDBT);
                wmma::load_matrix_sync(b1, bbase + k * 16 * LDBT + 16, LDBT);
                wmma::mma_sync(c0, afr[k], b0, c0);
                wmma::mma_sync(c1, afr[k], b1, c1);
            }
            wmma::store_matrix_sync(sKeys + wr * 16 * LDC + wc * 32, c0, LDC,
                                    wmma::mem_row_major);
            wmma::store_matrix_sync(sKeys + wr * 16 * LDC + wc * 32 + 16, c1, LDC,
                                    wmma::mem_row_major);
        }
        __syncthreads();

        // selection: 128 threads, one query each; float4 key reads
        if (tid < 128) {
            const unsigned long long* dmp =
                (const unsigned long long*)(smem + OFF_DM + st * 512);
            int jb = t * DT;
            const float4* row4 = (const float4*)(sKeys + tid * LDC);
            #pragma unroll 4
            for (int j4 = 0; j4 < DT / 4; ++j4) {
                float4 v4 = row4[j4];
                float kv[4] = {v4.x, v4.y, v4.z, v4.w};
                #pragma unroll
                for (int e = 0; e < 4; ++e) {
                    int j = j4 * 4 + e;
                    int p = __popcll(qm & dmp[j]);
                    float key = fmaxf(kv[e], 0.f) * sInv[p];
                    if (p > 0 && key < curMax)
                        cand_push(key, jb + j, sKeyL, sIdxL, gmax, curMax, tid);
                }
            }
        }
        __syncthreads();
        if (t < NT - 1) { CPWAIT0(); __syncthreads(); }
    }

    if (tid < 128) {
        #pragma unroll
        for (int i = 0; i < NCAND; ++i)
            g_cand[(size_t)(q0 + tid) * NCAND + i] = sIdxL[i * 128 + tid];
    }
}

// ---------------- phase 2: exact fp32 rescore + exact top-32 -------------
__global__ __launch_bounds__(256) void phase2_kernel(const float* __restrict__ X,
                                                     const float* __restrict__ F) {
    __shared__ float sx[4][64];
    __shared__ unsigned long long sqm[4];
    __shared__ float sk[4][64];
    __shared__ int   si[4][64];
    int ql = threadIdx.x >> 6, ci = threadIdx.x & 63;
    int q = blockIdx.x * 4 + ql;
    sx[ql][ci] = X[q * 64 + ci];
    if (ci == 0) sqm[ql] = g_qmask[q];
    __syncthreads();

    int cand = g_cand[(size_t)q * NCAND + ci];
    float key = INFF;
    if ((unsigned)cand < NF) {
        unsigned long long dm = g_dmask[cand];
        unsigned long long qmv = sqm[ql];
        const float4* frow = (const float4*)(F + (size_t)cand * 64);
        float acc = 0.f;
        #pragma unroll
        for (int d4 = 0; d4 < 16; ++d4) {
            float4 bq = frow[d4];
            float bb[4] = {bq.x, bq.y, bq.z, bq.w};
            #pragma unroll
            for (int e = 0; e < 4; ++e) {
                int d = d4 * 4 + e;
                float mbf = ((dm  >> d) & 1ull) ? 1.f : 0.f;
                float maf = ((qmv >> d) & 1ull) ? 1.f : 0.f;
                float a = (maf != 0.f) ? sx[ql][d] : 0.f;
                float b = (mbf != 0.f) ? bb[e] : 0.f;
                acc = fmaf(a * a, mbf, acc);
                acc = fmaf(maf, b * b, acc);
                acc = fmaf(-2.f * a, b, acc);
            }
        }
        int p = __popcll(qmv & dm);
        if (p > 0) key = fmaxf(acc, 0.f) * (1.0f / (float)p) * 64.f;
    } else cand = 0x7fffffff;
    sk[ql][ci] = key; si[ql][ci] = cand;
    __syncthreads();

    int rank = 0;
    for (int e = 0; e < 64; ++e) {
        float k2 = sk[ql][e]; int i2 = si[ql][e];
        bool less = (k2 < key) || (k2 == key && (i2 < cand || (i2 == cand && e < ci)));
        rank += less ? 1 : 0;
    }
    if (rank < NC) {
        g_ckey[(size_t)q * NC + rank] = key;
        g_cidx[(size_t)q * NC + rank] = cand;
    }
}

// ---------------- impute (verified R1) ------------------------------------
__global__ void impute_kernel(const float* __restrict__ X, const float* __restrict__ F,
                              float* __restrict__ out) {
    int warp = (blockIdx.x * blockDim.x + threadIdx.x) >> 5;
    int lane = threadIdx.x & 31;
    if (warp >= NQ) return;
    const int q = warp;

    float ck = g_ckey[q * NC + lane];
    int   ci = g_cidx[q * NC + lane];
    bool cfin = (ck < INFF);
    unsigned long long dm = 0ull;
    if (cfin) dm = g_dmask[ci];

    float x0 = X[q * 64 + lane], x1 = X[q * 64 + 32 + lane];
    float o0 = x0, o1 = x1;

    unsigned long long miss = ~g_qmask[q];
    while (miss) {
        int c = __ffsll((long long)miss) - 1;
        miss &= miss - 1;
        bool ok = cfin && ((dm >> c) & 1ull);
        float v = ok ? F[ci * 64 + c] : 0.f;
        unsigned m = __ballot_sync(0xffffffffu, ok);
        unsigned sel = 0; int cnt = 0;
        #pragma unroll
        for (int k = 0; k < KNN; ++k) {
            unsigned bb = m & (0u - m);
            sel |= bb; m ^= bb; cnt += (bb != 0u);
        }
        float contrib = ((sel >> lane) & 1u) ? v : 0.f;
        #pragma unroll
        for (int off = 16; off > 0; off >>= 1)
            contrib += __shfl_xor_sync(0xffffffffu, contrib, off);
        float imput = (cnt > 0) ? (contrib / (float)cnt) : g_colmean[c];
        if (lane == (c & 31)) { if (c < 32) o0 = imput; else o1 = imput; }
    }
    out[q * 64 + lane]      = o0;
    out[q * 64 + 32 + lane] = o1;
}

// ---------------- launch ----------------
extern "C" void kernel_launch(void* const* d_in, const int* in_sizes, int n_in,
                              void* d_out, int out_size) {
    const float* X = (const float*)d_in[0];
    const float* F = (const float*)d_in[1];
    float* out = (float*)d_out;

    masks_kernel<<<(NQ + NF) / 8, 256>>>(X, F);
    colmean_kernel<<<64, 256>>>(F);
    augA_kernel<<<NQ * 64 / 256, 256>>>(X);
    augBT_kernel<<<64 * NF / 256, 256>>>(F);

    cudaFuncSetAttribute(phase1_kernel, cudaFuncAttributeMaxDynamicSharedMemorySize, SMEM_P1);
    phase1_kernel<<<NQ / 128, 512, SMEM_P1>>>();

    phase2_kernel<<<NQ / 4, 256>>>(X, F);
    impute_kernel<<<NQ / 8, 256>>>(X, F, out);
}